// round 1
// baseline (speedup 1.0000x reference)
#include <cuda_runtime.h>
#include <math.h>

#define NR 32768
#define DM 256
#define NLAY 3
#define NSTEP 4
#define FFD 512
#define VOC 4096
#define KL 8

// ---------------- persistent device scratch (no allocations allowed) ----------------
__device__ float g_xt[NR * 4];
__device__ float g_code[NR];
__device__ int   g_gid[NR];
__device__ int   g_bin[NR];
__device__ float g_h[NR * DM];
__device__ float g_rot[NR * DM];
__device__ float g_qbuf[NR * DM];
__device__ float g_attno[NR * DM];
__device__ float g_d1[NR * DM];
__device__ float g_d2[NR * FFD];
__device__ float g_kc[NLAY * NSTEP * NR * DM];   // 402 MB
__device__ float g_vc[NLAY * NSTEP * NR * DM];   // 402 MB
__device__ float g_z[NR * 9];
__device__ float g_zarr[NSTEP * NR];
__device__ float g_qarr[NSTEP * NR];
__device__ float g_Hc[VOC * KL];
__device__ float g_Hm1[VOC];
__device__ float g_rat[VOC * KL];
__device__ unsigned g_mm[2];
__device__ float g_pdot[128];
__device__ float g_pclip[128];
__device__ float g_pvq[128];
__device__ float g_uni;

// ---------------- helpers ----------------
__device__ __forceinline__ unsigned f2u(float f) {
    unsigned u = __float_as_uint(f);
    return (u & 0x80000000u) ? ~u : (u | 0x80000000u);
}
__device__ __forceinline__ float u2f(unsigned u) {
    u = (u & 0x80000000u) ? (u & 0x7fffffffu) : ~u;
    return __uint_as_float(u);
}

// ---------------- init: xt = tanh(x @ Wp^T + bp), code/gid/ratios/uni ----------------
__global__ void k_init(const float* __restrict__ x, const float* __restrict__ pw,
                       const float* __restrict__ pb, const float* __restrict__ rat0) {
    int n = blockIdx.x * blockDim.x + threadIdx.x;
    if (n < NR) {
        int b = n >> 10, l = n & 1023;
        const float* xb = x + (size_t)b * 32768 + l;
        #pragma unroll
        for (int j = 0; j < 4; j++) {
            float acc = pb[j];
            #pragma unroll
            for (int cz = 0; cz < 32; cz++) acc += xb[cz * 1024] * pw[j * 32 + cz];
            g_xt[n * 4 + j] = tanhf(acc);
        }
        g_code[n] = 0.f;
        g_gid[n] = 0;
    }
    if (n < VOC * KL) g_rat[n] = rat0[n];
    if (n == 0) g_uni = 0.f;
}

// ---------------- embed current token: h = c*w0 + xi*w1 + b ----------------
__global__ void k_embed(const float* __restrict__ in_w, const float* __restrict__ in_b, int step) {
    int idx = blockIdx.x * blockDim.x + threadIdx.x;
    int n = idx >> 8, d = idx & 255;
    g_h[idx] = g_code[n] * in_w[2 * d] + g_xt[n * 4 + step] * in_w[2 * d + 1] + in_b[d];
}

// ---------------- rope at fixed position ----------------
__global__ void k_rope(int pos) {
    int idx = blockIdx.x * blockDim.x + threadIdx.x;   // NR*128
    int n = idx >> 7, k = idx & 127;
    float2 hv = *(const float2*)(g_h + (size_t)n * DM + 2 * k);
    float inv = powf(10000.f, -(float)(2 * k) / 256.f);
    float ang = (float)pos * inv;
    float c = cosf(ang), s = sinf(ang);
    float2 r;
    r.x = hv.x * c - hv.y * s;
    r.y = hv.y * c + hv.x * s;
    *(float2*)(g_rot + (size_t)n * DM + 2 * k) = r;
}

// ---------------- SGEMM: C[M,N] = A[M,K] @ W[N,K]^T + bias (opt relu) ----------------
__global__ void __launch_bounds__(256) k_gemm(const float* __restrict__ A,
                                              const float* __restrict__ W,
                                              const float* __restrict__ bias,
                                              float* __restrict__ C,
                                              int M, int N, int K, int relu) {
    __shared__ float As[16][128];
    __shared__ float Ws[16][64];
    const int bm = blockIdx.y * 128;
    const int bn = blockIdx.x * 64;
    const int tid = threadIdx.x;
    const int tx = tid & 15;
    const int ty = tid >> 4;
    float acc[8][4] = {};
    for (int k0 = 0; k0 < K; k0 += 16) {
        #pragma unroll
        for (int i = 0; i < 2; i++) {
            int idx = tid + i * 256;
            int row = idx >> 2;
            int kq = (idx & 3) << 2;
            float4 v = *(const float4*)(A + (size_t)(bm + row) * K + k0 + kq);
            As[kq + 0][row] = v.x; As[kq + 1][row] = v.y;
            As[kq + 2][row] = v.z; As[kq + 3][row] = v.w;
        }
        {
            int row = tid >> 2;
            int kq = (tid & 3) << 2;
            float4 v = *(const float4*)(W + (size_t)(bn + row) * K + k0 + kq);
            Ws[kq + 0][row] = v.x; Ws[kq + 1][row] = v.y;
            Ws[kq + 2][row] = v.z; Ws[kq + 3][row] = v.w;
        }
        __syncthreads();
        #pragma unroll
        for (int kk = 0; kk < 16; kk++) {
            float4 a0 = *(const float4*)&As[kk][ty * 8];
            float4 a1 = *(const float4*)&As[kk][ty * 8 + 4];
            float4 b0 = *(const float4*)&Ws[kk][tx * 4];
            float a[8] = {a0.x, a0.y, a0.z, a0.w, a1.x, a1.y, a1.z, a1.w};
            float b[4] = {b0.x, b0.y, b0.z, b0.w};
            #pragma unroll
            for (int m = 0; m < 8; m++)
                #pragma unroll
                for (int nn = 0; nn < 4; nn++) acc[m][nn] += a[m] * b[nn];
        }
        __syncthreads();
    }
    #pragma unroll
    for (int m = 0; m < 8; m++) {
        int row = bm + ty * 8 + m;
        #pragma unroll
        for (int nn = 0; nn < 4; nn++) {
            int col = bn + tx * 4 + nn;
            float v = acc[m][nn] + bias[col];
            if (relu) v = fmaxf(v, 0.f);
            C[(size_t)row * N + col] = v;
        }
    }
}

// ---------------- attention over cached K/V (one warp = one head) ----------------
__global__ void k_attn(int l, int npos) {
    int n = blockIdx.x;
    int lane = threadIdx.x & 31;
    int col = (threadIdx.x >> 5) * 32 + lane;   // head*32 + lane
    float q = g_qbuf[(size_t)n * DM + col];
    float s[4];
    float m = -1e30f;
    #pragma unroll
    for (int j = 0; j < 4; j++) {
        if (j < npos) {
            float kv = g_kc[((size_t)(l * NSTEP + j) * NR + n) * DM + col];
            float prod = q * kv;
            #pragma unroll
            for (int o = 16; o > 0; o >>= 1) prod += __shfl_xor_sync(0xffffffffu, prod, o);
            s[j] = prod / sqrtf(32.f);
            m = fmaxf(m, s[j]);
        }
    }
    float den = 0.f, o = 0.f;
    #pragma unroll
    for (int j = 0; j < 4; j++) {
        if (j < npos) {
            float p = expf(s[j] - m);
            den += p;
            o += p * g_vc[((size_t)(l * NSTEP + j) * NR + n) * DM + col];
        }
    }
    g_attno[(size_t)n * DM + col] = o / den;
}

// ---------------- residual + layernorm (one warp = one row), h updated in place ----------------
__global__ void k_ln(const float* __restrict__ delta, const float* __restrict__ gg,
                     const float* __restrict__ bb) {
    int warp = threadIdx.x >> 5, lane = threadIdx.x & 31;
    int n = blockIdx.x * 8 + warp;
    float v[8];
    float sum = 0.f;
    #pragma unroll
    for (int k = 0; k < 8; k++) {
        int c = k * 32 + lane;
        v[k] = g_h[(size_t)n * DM + c] + delta[(size_t)n * DM + c];
        sum += v[k];
    }
    #pragma unroll
    for (int o = 16; o > 0; o >>= 1) sum += __shfl_xor_sync(0xffffffffu, sum, o);
    float mu = sum / 256.f;
    float var = 0.f;
    #pragma unroll
    for (int k = 0; k < 8; k++) { float d = v[k] - mu; var += d * d; }
    #pragma unroll
    for (int o = 16; o > 0; o >>= 1) var += __shfl_xor_sync(0xffffffffu, var, o);
    var /= 256.f;
    float inv = 1.f / sqrtf(var + 1e-5f);
    #pragma unroll
    for (int k = 0; k < 8; k++) {
        int c = k * 32 + lane;
        g_h[(size_t)n * DM + c] = (v[k] - mu) * inv * gg[c] + bb[c];
    }
}

// ---------------- out projection z = h @ out_w^T + out_b (N x 9) ----------------
__global__ void k_outproj(const float* __restrict__ out_w, const float* __restrict__ out_b) {
    int warp = threadIdx.x >> 5, lane = threadIdx.x & 31;
    int n = blockIdx.x * 8 + warp;
    float hv[8];
    #pragma unroll
    for (int k = 0; k < 8; k++) hv[k] = g_h[(size_t)n * DM + k * 32 + lane];
    #pragma unroll
    for (int j = 0; j < 9; j++) {
        float acc = 0.f;
        #pragma unroll
        for (int k = 0; k < 8; k++) acc += hv[k] * out_w[j * DM + k * 32 + lane];
        #pragma unroll
        for (int o = 16; o > 0; o >>= 1) acc += __shfl_xor_sync(0xffffffffu, acc, o);
        if (lane == 0) g_z[n * 9 + j] = acc + out_b[j];
    }
}

// ---------------- min/max of z_pred over all rows ----------------
__global__ void k_mm_init() { g_mm[0] = 0xFFFFFFFFu; g_mm[1] = 0u; }

__global__ void k_minmax() {
    __shared__ unsigned smn[256], smx[256];
    int t = threadIdx.x;
    unsigned mn = 0xFFFFFFFFu, mx = 0u;
    for (int n = blockIdx.x * 256 + t; n < NR; n += gridDim.x * 256) {
        unsigned e = f2u(g_z[n * 9]);
        mn = (e < mn) ? e : mn;
        mx = (e > mx) ? e : mx;
    }
    smn[t] = mn; smx[t] = mx;
    __syncthreads();
    for (int s = 128; s > 0; s >>= 1) {
        if (t < s) {
            smn[t] = (smn[t + s] < smn[t]) ? smn[t + s] : smn[t];
            smx[t] = (smx[t + s] > smx[t]) ? smx[t + s] : smx[t];
        }
        __syncthreads();
    }
    if (t == 0) { atomicMin(&g_mm[0], smn[0]); atomicMax(&g_mm[1], smx[0]); }
}

// ---------------- bin assignment (first-match argmax semantics) ----------------
__global__ void k_bins(int step) {
    int n = blockIdx.x * blockDim.x + threadIdx.x;
    float MN = u2f(g_mm[0]);
    float MX = u2f(g_mm[1]);
    float x = g_z[n * 9];
    float bb[7];
    #pragma unroll
    for (int j = 0; j < 7; j++) bb[j] = g_z[n * 9 + 1 + j];
    int bin = -1;
    float xq = 0.f;
    #pragma unroll
    for (int j = 0; j < 8; j++) {
        float l = (j == 0) ? MN - 0.01f : bb[j - 1];
        float r = (j == 7) ? MX + 0.01f : bb[j];
        if (bin < 0 && x >= l && x < r && r > l) { bin = j; xq = (l + r) * 0.5f; }
    }
    g_bin[n] = bin;
    g_zarr[step * NR + n] = x;
    g_qarr[step * NR + n] = xq;
}

// ---------------- histogram (scatter-drop OOB, like jax) ----------------
__global__ void k_histzero() {
    int i = blockIdx.x * blockDim.x + threadIdx.x;
    if (i < VOC * KL) g_Hc[i] = 0.f;
    else if (i < VOC * KL + VOC) g_Hm1[i - VOC * KL] = 0.f;
}

__global__ void k_hist() {
    int n = blockIdx.x * 256 + threadIdx.x;
    int g = g_gid[n];
    if (g < 0 || g >= VOC) return;  // jax scatter drops OOB
    int bin = g_bin[n];
    if (bin >= 0) atomicAdd(&g_Hc[g * KL + bin], 1.f);
    else atomicAdd(&g_Hm1[g], 1.f);
}

// ---------------- ratios update ----------------
__global__ void k_ratupd() {
    int v = blockIdx.x * 256 + threadIdx.x;
    #pragma unroll
    for (int k = 0; k < 7; k++) {
        float hc = g_Hc[v * KL + k];
        if (hc > 0.f) g_rat[v * KL + k] = hc;
    }
    float hc7 = g_Hc[v * KL + 7], hm = g_Hm1[v], old7 = g_rat[v * KL + 7];
    g_rat[v * KL + 7] = hc7 > 0.f ? hc7 : (hm > 0.f ? hm : old7);
}

// ---------------- grad dot + order clip, update gid/code, deterministic partials ----------------
__global__ void __launch_bounds__(256) k_grad(int step) {
    __shared__ float sd[256], sc[256];
    int t = threadIdx.x;
    int n = blockIdx.x * 256 + t;
    int g = g_gid[n];
    g = g < 0 ? 0 : (g > VOC - 1 ? VOC - 1 : g);   // jax gather clamps OOB
    float r[8];
    #pragma unroll
    for (int k = 0; k < 8; k++) r[k] = g_rat[g * KL + k];
    float gr[7];
    float nrm = 0.f;
    #pragma unroll
    for (int k = 0; k < 7; k++) { gr[k] = -(r[k + 1] - r[k]); nrm += gr[k] * gr[k]; }
    nrm = sqrtf(nrm);
    float bby[7];
    #pragma unroll
    for (int k = 0; k < 7; k++) bby[k] = g_z[n * 9 + 1 + k];
    float dot = 0.f;
    #pragma unroll
    for (int k = 0; k < 7; k++) dot += bby[k] * (gr[k] / nrm);
    float cl = 0.f;
    #pragma unroll
    for (int k = 0; k < 6; k++) {
        float d = bby[k + 1] - bby[k];
        d = fmaxf(d, -9999999.f);
        d = fminf(d, 0.1f);
        cl += d;
    }
    int bin = g_bin[n];
    g_gid[n] += bin * (1 << (3 * step));
    g_code[n] = (float)bin;
    sd[t] = dot; sc[t] = cl;
    __syncthreads();
    for (int s = 128; s > 0; s >>= 1) {
        if (t < s) { sd[t] += sd[t + s]; sc[t] += sc[t + s]; }
        __syncthreads();
    }
    if (t == 0) { g_pdot[blockIdx.x] = sd[0]; g_pclip[blockIdx.x] = sc[0]; }
}

__global__ void k_losses() {
    __shared__ float sd[128], sc[128];
    int t = threadIdx.x;
    sd[t] = g_pdot[t]; sc[t] = g_pclip[t];
    __syncthreads();
    for (int s = 64; s > 0; s >>= 1) {
        if (t < s) { sd[t] += sd[t + s]; sc[t] += sc[t + s]; }
        __syncthreads();
    }
    if (t == 0) g_uni += sd[0] / (float)NR - sc[0] / ((float)NR * 6.f);
}

// ---------------- vq loss partials ----------------
__global__ void k_vqpart() {
    __shared__ float s[256];
    int t = threadIdx.x;
    int n = blockIdx.x * 256 + t;
    float acc = 0.f;
    #pragma unroll
    for (int j = 0; j < NSTEP; j++) {
        float d = g_qarr[j * NR + n] - g_zarr[j * NR + n];
        acc += d * d;
    }
    s[t] = acc;
    __syncthreads();
    for (int r = 128; r > 0; r >>= 1) {
        if (t < r) s[t] += s[t + r];
        __syncthreads();
    }
    if (t == 0) g_pvq[blockIdx.x] = s[0];
}

// ---------------- final projection to z_q ----------------
__global__ void k_zq(const float* __restrict__ ppw, const float* __restrict__ ppb,
                     float* __restrict__ out) {
    int t = blockIdx.x * blockDim.x + threadIdx.x;   // 0 .. 1048575
    int b = t >> 15;
    int rem = t & 32767;
    int cz = rem >> 10;
    int l = rem & 1023;
    int n = (b << 10) + l;
    float acc = ppb[cz];
    #pragma unroll
    for (int j = 0; j < 4; j++) {
        float q = g_qarr[j * NR + n], z = g_zarr[j * NR + n];
        float s = (q + z) - z;   // straight-through, matches jax fp exactly
        acc += s * ppw[cz * 4 + j];
    }
    out[t] = acc;
}

__global__ void k_scalars(float* __restrict__ out, int out_size) {
    __shared__ float s[128];
    int t = threadIdx.x;
    s[t] = g_pvq[t];
    __syncthreads();
    for (int r = 64; r > 0; r >>= 1) {
        if (t < r) s[t] += s[t + r];
        __syncthreads();
    }
    if (t == 0) {
        out[out_size - 2] = s[0] / (float)(NR * NSTEP);
        out[out_size - 1] = g_uni;
    }
}

// ---------------- host ----------------
static void gemm(const float* A, const float* W, const float* bias, float* C,
                 int M, int N, int K, int relu) {
    dim3 grid(N / 64, M / 128);
    k_gemm<<<grid, 256>>>(A, W, bias, C, M, N, K, relu);
}

extern "C" void kernel_launch(void* const* d_in, const int* in_sizes, int n_in,
                              void* d_out, int out_size) {
    const float* x     = (const float*)d_in[0];
    const float* ppvw  = (const float*)d_in[1];
    const float* ppvb  = (const float*)d_in[2];
    const float* ppow  = (const float*)d_in[3];
    const float* ppob  = (const float*)d_in[4];
    const float* in_w  = (const float*)d_in[5];
    const float* in_b  = (const float*)d_in[6];
    const float* out_w = (const float*)d_in[7];
    const float* out_b = (const float*)d_in[8];
    const float* qkv_w = (const float*)d_in[9];
    const float* qkv_b = (const float*)d_in[10];
    const float* ao_w  = (const float*)d_in[11];
    const float* ao_b  = (const float*)d_in[12];
    const float* f1_w  = (const float*)d_in[13];
    const float* f1_b  = (const float*)d_in[14];
    const float* f2_w  = (const float*)d_in[15];
    const float* f2_b  = (const float*)d_in[16];
    const float* ln1g  = (const float*)d_in[17];
    const float* ln1b  = (const float*)d_in[18];
    const float* ln2g  = (const float*)d_in[19];
    const float* ln2b  = (const float*)d_in[20];
    const float* rat0  = (const float*)d_in[21];
    float* out = (float*)d_out;

    float *h, *rot, *qb, *at_o, *d1, *d2, *kc, *vc;
    cudaGetSymbolAddress((void**)&h,    g_h);
    cudaGetSymbolAddress((void**)&rot,  g_rot);
    cudaGetSymbolAddress((void**)&qb,   g_qbuf);
    cudaGetSymbolAddress((void**)&at_o, g_attno);
    cudaGetSymbolAddress((void**)&d1,   g_d1);
    cudaGetSymbolAddress((void**)&d2,   g_d2);
    cudaGetSymbolAddress((void**)&kc,   g_kc);
    cudaGetSymbolAddress((void**)&vc,   g_vc);

    k_init<<<NR / 256, 256>>>(x, ppvw, ppvb, rat0);

    for (int i = 0; i < NSTEP; i++) {
        k_embed<<<NR * DM / 256, 256>>>(in_w, in_b, i);
        for (int l = 0; l < NLAY; l++) {
            k_rope<<<NR * 128 / 256, 256>>>(i);
            const float* Wl = qkv_w + (size_t)l * 768 * DM;
            const float* bl = qkv_b + l * 768;
            float* kslot = kc + (size_t)(l * NSTEP + i) * NR * DM;
            float* vslot = vc + (size_t)(l * NSTEP + i) * NR * DM;
            gemm(rot, Wl,            bl,       qb,    NR, DM, DM, 0);   // Q
            gemm(rot, Wl + 256 * DM, bl + 256, kslot, NR, DM, DM, 0);   // K -> cache
            gemm(h,   Wl + 512 * DM, bl + 512, vslot, NR, DM, DM, 0);   // V -> cache
            k_attn<<<NR, 256>>>(l, i + 1);
            gemm(at_o, ao_w + (size_t)l * DM * DM, ao_b + l * DM, d1, NR, DM, DM, 0);
            k_ln<<<NR / 8, 256>>>(d1, ln1g + l * DM, ln1b + l * DM);
            gemm(h,  f1_w + (size_t)l * FFD * DM, f1_b + l * FFD, d2, NR, FFD, DM, 1);
            gemm(d2, f2_w + (size_t)l * DM * FFD, f2_b + l * DM,  d1, NR, DM, FFD, 0);
            k_ln<<<NR / 8, 256>>>(d1, ln2g + l * DM, ln2b + l * DM);
        }
        k_outproj<<<NR / 8, 256>>>(out_w, out_b);
        k_mm_init<<<1, 1>>>();
        k_minmax<<<64, 256>>>();
        k_bins<<<NR / 256, 256>>>(i);
        k_histzero<<<(VOC * KL + VOC + 255) / 256, 256>>>();
        k_hist<<<NR / 256, 256>>>();
        k_ratupd<<<VOC / 256, 256>>>();
        k_grad<<<128, 256>>>(i);
        k_losses<<<1, 128>>>();
    }

    k_vqpart<<<128, 256>>>();
    k_zq<<<(NR * 32) / 256, 256>>>(ppow, ppob, out);
    k_scalars<<<1, 128>>>(out, out_size);
}